// round 4
// baseline (speedup 1.0000x reference)
#include <cuda_runtime.h>
#include <math.h>

// LIF scan: B=8, T=64, C=64, H=32, W=32.
// One thread per 2 consecutive CHW elements (float2) -> 262144 threads,
// 1024 blocks: ~6.9 blocks/SM (occ ~83%, wave imbalance ~1%).
// T loop chunked by 4 with loads batched into a local array so ptxas
// front-issues 4 independent LDG.64 per chunk (MLP).

#define B_ 8
#define T_ 64
#define CHW_ 65536              // 64*32*32
#define CHW2_ (CHW_ / 2)        // 32768 float2 per (b,t) slab
#define N2_ (B_ * CHW2_)        // 262144 threads
#define CHUNK_ 4

__global__ __launch_bounds__(256) void lif_scan_kernel(
    const float2* __restrict__ x,        // [B*T*CHW2] float2
    const float2* __restrict__ vth_raw,  // [CHW2]
    const float2* __restrict__ decay_raw,// [CHW2]
    const float* __restrict__ hp_v_m,
    const float* __restrict__ hp_v_s,
    const float* __restrict__ hp_d_m,
    const float* __restrict__ hp_d_s,
    float2* __restrict__ out)            // [B*T*CHW2] float2
{
    int tid = blockIdx.x * blockDim.x + threadIdx.x;
    if (tid >= N2_) return;

    int b = tid >> 15;          // tid / CHW2_
    int j = tid & (CHW2_ - 1);  // tid % CHW2_

    float vm = *hp_v_m, vs = *hp_v_s;
    float dm = *hp_d_m, ds = *hp_d_s;

    float2 vr = vth_raw[j];
    float2 dr = decay_raw[j];

    float vth[2], dec[2];
    {
        float z[2] = {vr.x * vs + vm, vr.y * vs + vm};
        float d[2] = {dr.x * ds + dm, dr.y * ds + dm};
        #pragma unroll
        for (int k = 0; k < 2; k++) {
            float zz = z[k];
            float sp = (zz > 20.0f) ? zz : log1pf(__expf(zz));
            vth[k] = sp + 0.5f;
            float sg = 1.0f / (1.0f + __expf(-d[k]));
            dec[k] = fminf(fmaxf(sg, 0.0f), 0.99f);
        }
    }

    const float2* xp = x + (size_t)b * T_ * CHW2_ + j;
    float2* op = out + (size_t)b * T_ * CHW2_ + j;

    float v0 = 0.f, v1 = 0.f;

    #pragma unroll
    for (int t0 = 0; t0 < T_; t0 += CHUNK_) {
        // Batch CHUNK_ independent loads (front-issued by ptxas).
        float2 xs[CHUNK_];
        #pragma unroll
        for (int i = 0; i < CHUNK_; i++)
            xs[i] = xp[(size_t)(t0 + i) * CHW2_];

        float2 ss[CHUNK_];
        #pragma unroll
        for (int i = 0; i < CHUNK_; i++) {
            float vv0 = fmaf(v0, dec[0], xs[i].x);
            float vv1 = fmaf(v1, dec[1], xs[i].y);
            float s0 = (vv0 - vth[0] > 0.0f) ? 1.0f : 0.0f;
            float s1 = (vv1 - vth[1] > 0.0f) ? 1.0f : 0.0f;
            v0 = vv0 - s0 * vth[0];
            v1 = vv1 - s1 * vth[1];
            ss[i] = make_float2(s0, s1);
        }

        #pragma unroll
        for (int i = 0; i < CHUNK_; i++)
            op[(size_t)(t0 + i) * CHW2_] = ss[i];
    }
}

extern "C" void kernel_launch(void* const* d_in, const int* in_sizes, int n_in,
                              void* d_out, int out_size)
{
    const float2* x         = (const float2*)d_in[0];
    const float2* vth_raw   = (const float2*)d_in[1];
    const float2* decay_raw = (const float2*)d_in[2];
    const float*  hp_v_m    = (const float*)d_in[3];
    const float*  hp_v_s    = (const float*)d_in[4];
    const float*  hp_d_m    = (const float*)d_in[5];
    const float*  hp_d_s    = (const float*)d_in[6];
    // d_in[7] = hp_alpha, unused in forward
    float2* out = (float2*)d_out;

    int threads = 256;
    int blocks = N2_ / threads;  // 1024
    lif_scan_kernel<<<blocks, threads>>>(x, vth_raw, decay_raw,
                                         hp_v_m, hp_v_s, hp_d_m, hp_d_s, out);
}

// round 6
// speedup vs baseline: 1.0091x; 1.0091x over previous
#include <cuda_runtime.h>
#include <math.h>

// LIF scan: B=8, T=64, C=64, H=32, W=32.
// float2 per thread (262144 threads), 2048 blocks of 128.
// T loop chunked by 8: 8 back-to-back streaming LDG.64, compute, 8
// back-to-back streaming STG.64 -> long same-direction DRAM bursts
// (fewer bus turnarounds), L2 evict-first on both touch-once streams.

#define B_ 8
#define T_ 64
#define CHW_ 65536              // 64*32*32
#define CHW2_ (CHW_ / 2)        // 32768 float2 per (b,t) slab
#define N2_ (B_ * CHW2_)        // 262144 threads
#define CHUNK_ 8

__global__ __launch_bounds__(128) void lif_scan_kernel(
    const float2* __restrict__ x,        // [B*T*CHW2] float2
    const float2* __restrict__ vth_raw,  // [CHW2]
    const float2* __restrict__ decay_raw,// [CHW2]
    const float* __restrict__ hp_v_m,
    const float* __restrict__ hp_v_s,
    const float* __restrict__ hp_d_m,
    const float* __restrict__ hp_d_s,
    float2* __restrict__ out)            // [B*T*CHW2] float2
{
    int tid = blockIdx.x * blockDim.x + threadIdx.x;
    if (tid >= N2_) return;

    int b = tid >> 15;          // tid / CHW2_
    int j = tid & (CHW2_ - 1);  // tid % CHW2_

    float vm = *hp_v_m, vs = *hp_v_s;
    float dm = *hp_d_m, ds = *hp_d_s;

    float2 vr = vth_raw[j];
    float2 dr = decay_raw[j];

    float vth0, vth1, dec0, dec1;
    {
        float z0 = vr.x * vs + vm, z1 = vr.y * vs + vm;
        float d0 = dr.x * ds + dm, d1 = dr.y * ds + dm;
        vth0 = ((z0 > 20.0f) ? z0 : log1pf(__expf(z0))) + 0.5f;
        vth1 = ((z1 > 20.0f) ? z1 : log1pf(__expf(z1))) + 0.5f;
        dec0 = fminf(fmaxf(1.0f / (1.0f + __expf(-d0)), 0.0f), 0.99f);
        dec1 = fminf(fmaxf(1.0f / (1.0f + __expf(-d1)), 0.0f), 0.99f);
    }

    const float2* xp = x + (size_t)b * T_ * CHW2_ + j;
    float2* op = out + (size_t)b * T_ * CHW2_ + j;

    float v0 = 0.f, v1 = 0.f;

    #pragma unroll
    for (int t0 = 0; t0 < T_; t0 += CHUNK_) {
        // 8 independent streaming loads, front-issued back-to-back.
        float2 xs[CHUNK_];
        #pragma unroll
        for (int i = 0; i < CHUNK_; i++)
            xs[i] = __ldcs(xp + (size_t)(t0 + i) * CHW2_);

        float2 ss[CHUNK_];
        #pragma unroll
        for (int i = 0; i < CHUNK_; i++) {
            float vv0 = fmaf(v0, dec0, xs[i].x);
            float vv1 = fmaf(v1, dec1, xs[i].y);
            float s0 = (vv0 - vth0 > 0.0f) ? 1.0f : 0.0f;
            float s1 = (vv1 - vth1 > 0.0f) ? 1.0f : 0.0f;
            v0 = vv0 - s0 * vth0;
            v1 = vv1 - s1 * vth1;
            ss[i] = make_float2(s0, s1);
        }

        // 8 streaming stores back-to-back.
        #pragma unroll
        for (int i = 0; i < CHUNK_; i++)
            __stcs(op + (size_t)(t0 + i) * CHW2_, ss[i]);
    }
}

extern "C" void kernel_launch(void* const* d_in, const int* in_sizes, int n_in,
                              void* d_out, int out_size)
{
    const float2* x         = (const float2*)d_in[0];
    const float2* vth_raw   = (const float2*)d_in[1];
    const float2* decay_raw = (const float2*)d_in[2];
    const float*  hp_v_m    = (const float*)d_in[3];
    const float*  hp_v_s    = (const float*)d_in[4];
    const float*  hp_d_m    = (const float*)d_in[5];
    const float*  hp_d_s    = (const float*)d_in[6];
    // d_in[7] = hp_alpha, unused in forward
    float2* out = (float2*)d_out;

    int threads = 128;
    int blocks = N2_ / threads;  // 2048
    lif_scan_kernel<<<blocks, threads>>>(x, vth_raw, decay_raw,
                                         hp_v_m, hp_v_s, hp_d_m, hp_d_s, out);
}

// round 7
// speedup vs baseline: 1.0240x; 1.0148x over previous
#include <cuda_runtime.h>
#include <math.h>

// LIF scan: B=8, T=64, C=64, H=32, W=32.
// Best-measured config (R4): float2 per thread, 1024 blocks x 256 (occ ~79%).
// CHUNK=8 batched default-cached loads/stores (long same-direction bursts);
// NO streaming hints (measured -3% DRAM in R2/R6). 32-bit addressing.

#define B_ 8
#define T_ 64
#define CHW_ 65536              // 64*32*32
#define CHW2_ (CHW_ / 2)        // 32768 float2 per (b,t) slab
#define N2_ (B_ * CHW2_)        // 262144 threads
#define CHUNK_ 8

__global__ __launch_bounds__(256) void lif_scan_kernel(
    const float2* __restrict__ x,        // [B*T*CHW2] float2
    const float2* __restrict__ vth_raw,  // [CHW2]
    const float2* __restrict__ decay_raw,// [CHW2]
    const float* __restrict__ hp_v_m,
    const float* __restrict__ hp_v_s,
    const float* __restrict__ hp_d_m,
    const float* __restrict__ hp_d_s,
    float2* __restrict__ out)            // [B*T*CHW2] float2
{
    int tid = blockIdx.x * blockDim.x + threadIdx.x;
    if (tid >= N2_) return;

    int b = tid >> 15;          // tid / CHW2_
    int j = tid & (CHW2_ - 1);  // tid % CHW2_

    float vm = *hp_v_m, vs = *hp_v_s;
    float dm = *hp_d_m, ds = *hp_d_s;

    float2 vr = vth_raw[j];
    float2 dr = decay_raw[j];

    float vth0, vth1, dec0, dec1;
    {
        float z0 = vr.x * vs + vm, z1 = vr.y * vs + vm;
        float d0 = dr.x * ds + dm, d1 = dr.y * ds + dm;
        vth0 = ((z0 > 20.0f) ? z0 : log1pf(__expf(z0))) + 0.5f;
        vth1 = ((z1 > 20.0f) ? z1 : log1pf(__expf(z1))) + 0.5f;
        dec0 = fminf(fmaxf(1.0f / (1.0f + __expf(-d0)), 0.0f), 0.99f);
        dec1 = fminf(fmaxf(1.0f / (1.0f + __expf(-d1)), 0.0f), 0.99f);
    }

    // 32-bit offsets: max offset = B*T*CHW2 = 2^24 float2 < 2^31.
    unsigned base = (unsigned)b * (T_ * CHW2_) + (unsigned)j;
    const float2* xp = x + base;
    float2* op = out + base;

    float v0 = 0.f, v1 = 0.f;

    #pragma unroll
    for (int t0 = 0; t0 < T_; t0 += CHUNK_) {
        // 8 independent loads, front-issued back-to-back (default caching).
        float2 xs[CHUNK_];
        #pragma unroll
        for (int i = 0; i < CHUNK_; i++)
            xs[i] = xp[(unsigned)(t0 + i) * CHW2_];

        float2 ss[CHUNK_];
        #pragma unroll
        for (int i = 0; i < CHUNK_; i++) {
            float vv0 = fmaf(v0, dec0, xs[i].x);
            float vv1 = fmaf(v1, dec1, xs[i].y);
            float s0 = (vv0 - vth0 > 0.0f) ? 1.0f : 0.0f;
            float s1 = (vv1 - vth1 > 0.0f) ? 1.0f : 0.0f;
            v0 = vv0 - s0 * vth0;
            v1 = vv1 - s1 * vth1;
            ss[i] = make_float2(s0, s1);
        }

        // 8 stores back-to-back.
        #pragma unroll
        for (int i = 0; i < CHUNK_; i++)
            op[(unsigned)(t0 + i) * CHW2_] = ss[i];
    }
}

extern "C" void kernel_launch(void* const* d_in, const int* in_sizes, int n_in,
                              void* d_out, int out_size)
{
    const float2* x         = (const float2*)d_in[0];
    const float2* vth_raw   = (const float2*)d_in[1];
    const float2* decay_raw = (const float2*)d_in[2];
    const float*  hp_v_m    = (const float*)d_in[3];
    const float*  hp_v_s    = (const float*)d_in[4];
    const float*  hp_d_m    = (const float*)d_in[5];
    const float*  hp_d_s    = (const float*)d_in[6];
    // d_in[7] = hp_alpha, unused in forward
    float2* out = (float2*)d_out;

    int threads = 256;
    int blocks = N2_ / threads;  // 1024
    lif_scan_kernel<<<blocks, threads>>>(x, vth_raw, decay_raw,
                                         hp_v_m, hp_v_s, hp_d_m, hp_d_s, out);
}